// round 1
// baseline (speedup 1.0000x reference)
#include <cuda_runtime.h>

#define BATCH 4
#define CH    128
#define HW    4096   // 64*64
#define RB    64     // row-blocks in scores grid (HW/64)

// ---------------- scratch (static device memory; no allocations) -------------
__device__ float g_Q[BATCH * CH * HW];            // 8 MB  (layout [b][c][i])
__device__ float g_K[BATCH * CH * HW];            // 8 MB
__device__ float g_V[BATCH * CH * HW];            // 8 MB  (becomes V/colsum in-place)
__device__ float g_E[(size_t)BATCH * HW * HW];    // 268 MB exp(scores) [b][i][j]
__device__ float g_colpart[BATCH * RB * HW];      // 4 MB  per-rowblock col sums
__device__ float g_colsum[BATCH * HW];            // 64 KB

// ---------------------------------------------------------------------------
// Kernel 1: QKV projection.  out[b][o][i] = sum_c W[o][c] * X[b][c][i] + bias[o]
// grid: (HW/32, 3, BATCH), block: 128 threads (one per output channel o)
// ---------------------------------------------------------------------------
__global__ void proj_kernel(const float* __restrict__ X,
                            const float* __restrict__ Wq, const float* __restrict__ bq,
                            const float* __restrict__ Wk, const float* __restrict__ bk,
                            const float* __restrict__ Wv, const float* __restrict__ bv)
{
    const int p  = blockIdx.y;
    const float* W    = (p == 0) ? Wq : (p == 1) ? Wk : Wv;
    const float* bias = (p == 0) ? bq : (p == 1) ? bk : bv;
    float* out        = (p == 0) ? g_Q : (p == 1) ? g_K : g_V;

    const int b  = blockIdx.z;
    const int i0 = blockIdx.x * 32;
    const int o  = threadIdx.x;           // 0..127

    __shared__ float Xs[CH][32];          // 16 KB
    // cooperative load of X tile: [c][ii]
    for (int idx = threadIdx.x; idx < CH * 32; idx += 128) {
        int c  = idx >> 5;
        int ii = idx & 31;
        Xs[c][ii] = X[((size_t)b * CH + c) * HW + i0 + ii];
    }
    __syncthreads();

    float acc[32];
#pragma unroll
    for (int ii = 0; ii < 32; ii++) acc[ii] = 0.f;

    for (int c = 0; c < CH; c += 4) {
        float4 w4 = *reinterpret_cast<const float4*>(&W[o * CH + c]);
        float w[4] = {w4.x, w4.y, w4.z, w4.w};
#pragma unroll
        for (int cc = 0; cc < 4; cc++) {
#pragma unroll
            for (int ii = 0; ii < 32; ii++)
                acc[ii] += w[cc] * Xs[c + cc][ii];
        }
    }
    const float bo = bias[o];
    float* op = &out[((size_t)b * CH + o) * HW + i0];
#pragma unroll
    for (int ii = 0; ii < 32; ii++) op[ii] = acc[ii] + bo;
}

// ---------------------------------------------------------------------------
// Kernel 2: E[b][i][j] = exp( sum_c Q[b][c][i] * K[b][c][j] )
//           + deterministic per-rowblock partial column sums.
// grid: (HW/64, HW/64, BATCH), block: 256 threads, 64x64 tile, 4x4 per thread.
// ---------------------------------------------------------------------------
__global__ void scores_kernel()
{
    const int b  = blockIdx.z;
    const int i0 = blockIdx.y * 64;   // query rows
    const int j0 = blockIdx.x * 64;   // key cols
    const int tx = threadIdx.x & 15;
    const int ty = threadIdx.x >> 4;

    __shared__ float Qs[16][68];
    __shared__ float Ks[16][68];

    const float* Qb = g_Q + (size_t)b * CH * HW;
    const float* Kb = g_K + (size_t)b * CH * HW;

    float acc[4][4];
#pragma unroll
    for (int r = 0; r < 4; r++)
#pragma unroll
        for (int c = 0; c < 4; c++) acc[r][c] = 0.f;

    for (int kk = 0; kk < CH; kk += 16) {
#pragma unroll
        for (int r = 0; r < 4; r++) {
            int idx = threadIdx.x + r * 256;
            int t   = idx >> 6;
            int col = idx & 63;
            Qs[t][col] = Qb[(size_t)(kk + t) * HW + i0 + col];
            Ks[t][col] = Kb[(size_t)(kk + t) * HW + j0 + col];
        }
        __syncthreads();
#pragma unroll
        for (int k = 0; k < 16; k++) {
            float4 a4  = *reinterpret_cast<float4*>(&Qs[k][ty * 4]);
            float4 b4  = *reinterpret_cast<float4*>(&Ks[k][tx * 4]);
            float a[4] = {a4.x, a4.y, a4.z, a4.w};
            float bb[4] = {b4.x, b4.y, b4.z, b4.w};
#pragma unroll
            for (int r = 0; r < 4; r++)
#pragma unroll
                for (int c = 0; c < 4; c++)
                    acc[r][c] += a[r] * bb[c];
        }
        __syncthreads();
    }

    // exp + store + per-thread column partials
    float csum[4] = {0.f, 0.f, 0.f, 0.f};
    const size_t Ebase = (size_t)b * HW * HW;
#pragma unroll
    for (int r = 0; r < 4; r++) {
        float e0 = __expf(acc[r][0]);
        float e1 = __expf(acc[r][1]);
        float e2 = __expf(acc[r][2]);
        float e3 = __expf(acc[r][3]);
        csum[0] += e0; csum[1] += e1; csum[2] += e2; csum[3] += e3;
        float4 ev = make_float4(e0, e1, e2, e3);
        size_t row = Ebase + (size_t)(i0 + ty * 4 + r) * HW;
        *reinterpret_cast<float4*>(&g_E[row + j0 + tx * 4]) = ev;
    }

    // reduce csum over the 16 ty rows (deterministic, no atomics)
    __shared__ float red[16][64];
    __syncthreads();
#pragma unroll
    for (int c = 0; c < 4; c++) red[ty][tx * 4 + c] = csum[c];
    __syncthreads();
    if (threadIdx.x < 64) {
        float s = 0.f;
#pragma unroll
        for (int t = 0; t < 16; t++) s += red[t][threadIdx.x];
        g_colpart[((b * RB) + (i0 >> 6)) * HW + j0 + threadIdx.x] = s;
    }
}

// ---------------------------------------------------------------------------
// Kernel 3: colsum[b][j] = sum_rb colpart[b][rb][j]
// ---------------------------------------------------------------------------
__global__ void colsum_kernel()
{
    int tid = blockIdx.x * blockDim.x + threadIdx.x;   // 0 .. BATCH*HW-1
    if (tid >= BATCH * HW) return;
    int b = tid / HW;
    int j = tid % HW;
    float s = 0.f;
#pragma unroll 8
    for (int rb = 0; rb < RB; rb++)
        s += g_colpart[((b * RB) + rb) * HW + j];
    g_colsum[tid] = s;
}

// ---------------------------------------------------------------------------
// Kernel 4: V[b][c][j] /= colsum[b][j]   (in-place; V rewritten every launch)
// ---------------------------------------------------------------------------
__global__ void vnorm_kernel()
{
    int idx = blockIdx.x * blockDim.x + threadIdx.x;   // 0 .. BATCH*CH*HW-1
    if (idx >= BATCH * CH * HW) return;
    int j = idx & (HW - 1);
    int b = idx / (CH * HW);
    g_V[idx] = g_V[idx] / g_colsum[b * HW + j];
}

// ---------------------------------------------------------------------------
// Kernel 5: out[b][c][i] = X[b][c][i] + sum_j E[b][i][j] * V'[b][c][j]
// grid: (HW/64, CH/64, BATCH), block: 256 threads, 64(i) x 64(c) tile.
// ---------------------------------------------------------------------------
__global__ void av_kernel(const float* __restrict__ X, float* __restrict__ out)
{
    const int b  = blockIdx.z;
    const int c0 = blockIdx.y * 64;
    const int i0 = blockIdx.x * 64;
    const int tx = threadIdx.x & 15;   // i direction
    const int ty = threadIdx.x >> 4;   // c direction

    __shared__ float Es[16][68];       // [jl][il]
    __shared__ float Vs[16][68];       // [jl][cl]

    const float* Eb = g_E + (size_t)b * HW * HW;
    const float* Vb = g_V + (size_t)b * CH * HW;

    float acc[4][4];                   // [cc][ii]
#pragma unroll
    for (int c = 0; c < 4; c++)
#pragma unroll
        for (int i = 0; i < 4; i++) acc[c][i] = 0.f;

    for (int jt = 0; jt < HW; jt += 16) {
#pragma unroll
        for (int r = 0; r < 4; r++) {
            int idx = threadIdx.x + r * 256;
            int l   = idx >> 4;        // 0..63 (il / cl)
            int jl  = idx & 15;
            Es[jl][l] = Eb[(size_t)(i0 + l) * HW + jt + jl];
            Vs[jl][l] = Vb[(size_t)(c0 + l) * HW + jt + jl];
        }
        __syncthreads();
#pragma unroll
        for (int jl = 0; jl < 16; jl++) {
            float4 a4 = *reinterpret_cast<float4*>(&Es[jl][tx * 4]);
            float4 b4 = *reinterpret_cast<float4*>(&Vs[jl][ty * 4]);
            float a[4]  = {a4.x, a4.y, a4.z, a4.w};
            float bb[4] = {b4.x, b4.y, b4.z, b4.w};
#pragma unroll
            for (int c = 0; c < 4; c++)
#pragma unroll
                for (int i = 0; i < 4; i++)
                    acc[c][i] += bb[c] * a[i];
        }
        __syncthreads();
    }

    // epilogue: residual add + store
#pragma unroll
    for (int c = 0; c < 4; c++) {
        size_t base = ((size_t)b * CH + c0 + ty * 4 + c) * HW + i0 + tx * 4;
        float4 xv = *reinterpret_cast<const float4*>(&X[base]);
        float4 ov = make_float4(xv.x + acc[c][0], xv.y + acc[c][1],
                                xv.z + acc[c][2], xv.w + acc[c][3]);
        *reinterpret_cast<float4*>(&out[base]) = ov;
    }
}

// ---------------------------------------------------------------------------
extern "C" void kernel_launch(void* const* d_in, const int* in_sizes, int n_in,
                              void* d_out, int out_size)
{
    const float* X  = (const float*)d_in[0];
    const float* Wq = (const float*)d_in[1];
    const float* bq = (const float*)d_in[2];
    const float* Wk = (const float*)d_in[3];
    const float* bk = (const float*)d_in[4];
    const float* Wv = (const float*)d_in[5];
    const float* bv = (const float*)d_in[6];
    float* out = (float*)d_out;

    proj_kernel<<<dim3(HW / 32, 3, BATCH), 128>>>(X, Wq, bq, Wk, bk, Wv, bv);
    scores_kernel<<<dim3(HW / 64, HW / 64, BATCH), 256>>>();
    colsum_kernel<<<(BATCH * HW) / 256, 256>>>();
    vnorm_kernel<<<(BATCH * CH * HW) / 256, 256>>>();
    av_kernel<<<dim3(HW / 64, CH / 64, BATCH), 256>>>(X, out);
}

// round 4
// speedup vs baseline: 2.2528x; 2.2528x over previous
#include <cuda_runtime.h>
#include <cuda_bf16.h>
#include <cstdint>

#define BATCH 4
#define CH    128
#define HW    4096
#define RB    32

typedef __nv_bfloat16 bf16;

// ---------------- scratch (static device memory) ----------------------------
__device__ bf16  g_Qhi[BATCH * HW * CH];           // [b][i][c]
__device__ bf16  g_Qlo[BATCH * HW * CH];
__device__ bf16  g_Khi[BATCH * HW * CH];           // [b][j][c]
__device__ bf16  g_Klo[BATCH * HW * CH];
__device__ float g_V  [BATCH * CH * HW];           // [b][c][j]
__device__ bf16  g_Vhi[BATCH * CH * HW];           // V/colsum split
__device__ bf16  g_Vlo[BATCH * CH * HW];
__device__ bf16  g_Ehi[(size_t)BATCH * HW * HW];   // exp(scores) hi  [b][i][j]
__device__ bf16  g_Elo[(size_t)BATCH * HW * HW];   // exp(scores) lo
__device__ float g_colpart[BATCH * RB * HW];
__device__ float g_colsum[BATCH * HW];

// ---------------- helpers ----------------------------------------------------
__device__ __forceinline__ uint32_t smem_u32(const void* p) {
    uint32_t a;
    asm("{ .reg .u64 t; cvta.to.shared.u64 t, %1; cvt.u32.u64 %0, t; }" : "=r"(a) : "l"(p));
    return a;
}
__device__ __forceinline__ uint32_t lds32(uint32_t a) {
    uint32_t v;
    asm volatile("ld.shared.b32 %0, [%1];" : "=r"(v) : "r"(a));
    return v;
}
__device__ __forceinline__ void cp16(uint32_t dst, const void* src) {
    asm volatile("cp.async.cg.shared.global [%0], [%1], 16;" :: "r"(dst), "l"(src) : "memory");
}
__device__ __forceinline__ void cp_commit() {
    asm volatile("cp.async.commit_group;" ::: "memory");
}
template<int N> __device__ __forceinline__ void cp_wait() {
    asm volatile("cp.async.wait_group %0;" :: "n"(N) : "memory");
}
// D += A(row,m16k16 bf16) * B(col,k16n8 bf16), fp32 accum
__device__ __forceinline__ void mma_bf16(float* c, const uint32_t* a, const uint32_t* b) {
    asm volatile(
        "mma.sync.aligned.m16n8k16.row.col.f32.bf16.bf16.f32 "
        "{%0,%1,%2,%3}, {%4,%5,%6,%7}, {%8,%9}, {%0,%1,%2,%3};"
        : "+f"(c[0]), "+f"(c[1]), "+f"(c[2]), "+f"(c[3])
        : "r"(a[0]), "r"(a[1]), "r"(a[2]), "r"(a[3]), "r"(b[0]), "r"(b[1]));
}
__device__ __forceinline__ void split_bf16(float v, bf16& h, bf16& l) {
    h = __float2bfloat16(v);
    l = __float2bfloat16(v - __bfloat162float(h));
}

// SMEM tile geometry: 128 rows x 32 bf16, row stride 40 bf16 (80 B) -> conflict-free
#define TROW  80
#define TILE  10240      // 128*80
#define STAGE 40960      // 4 tiles

// ---------------------------------------------------------------------------
// Kernel 1: QKV projection.
// ---------------------------------------------------------------------------
__global__ void proj_kernel(const float* __restrict__ X,
                            const float* __restrict__ Wq, const float* __restrict__ bq,
                            const float* __restrict__ Wk, const float* __restrict__ bk,
                            const float* __restrict__ Wv, const float* __restrict__ bv)
{
    const int p  = blockIdx.y;
    const float* W    = (p == 0) ? Wq : (p == 1) ? Wk : Wv;
    const float* bias = (p == 0) ? bq : (p == 1) ? bk : bv;

    const int b  = blockIdx.z;
    const int i0 = blockIdx.x * 32;
    const int o  = threadIdx.x;

    __shared__ float Xs[CH][32];
    __shared__ float T[32][132];

    for (int idx = threadIdx.x; idx < CH * 32; idx += 128) {
        int c  = idx >> 5;
        int ii = idx & 31;
        Xs[c][ii] = X[((size_t)b * CH + c) * HW + i0 + ii];
    }
    __syncthreads();

    float acc[32];
#pragma unroll
    for (int ii = 0; ii < 32; ii++) acc[ii] = 0.f;
    for (int c = 0; c < CH; c += 4) {
        float4 w4 = *reinterpret_cast<const float4*>(&W[o * CH + c]);
        float w[4] = {w4.x, w4.y, w4.z, w4.w};
#pragma unroll
        for (int cc = 0; cc < 4; cc++)
#pragma unroll
            for (int ii = 0; ii < 32; ii++)
                acc[ii] += w[cc] * Xs[c + cc][ii];
    }
    const float bo = bias[o];

    if (p == 2) {
        float* op = &g_V[((size_t)b * CH + o) * HW + i0];
#pragma unroll
        for (int ii = 0; ii < 32; ii++) op[ii] = acc[ii] + bo;
    } else {
#pragma unroll
        for (int ii = 0; ii < 32; ii++) T[ii][o] = acc[ii] + bo;
        __syncthreads();
        bf16* hi = (p == 0) ? g_Qhi : g_Khi;
        bf16* lo = (p == 0) ? g_Qlo : g_Klo;
        // cover all 32 rows x 128 channels: 2048 bf16x2 pairs, 128 threads x 16
#pragma unroll
        for (int k = 0; k < 16; k++) {
            int gi  = threadIdx.x + k * 128;   // 0..2047
            int row = gi >> 6;                 // 0..31
            int cp  = (gi & 63) * 2;           // 0..126
            float v0 = T[row][cp];
            float v1 = T[row][cp + 1];
            bf16 h0, l0, h1, l1;
            split_bf16(v0, h0, l0);
            split_bf16(v1, h1, l1);
            size_t base = ((size_t)b * HW + i0 + row) * CH + cp;
            *reinterpret_cast<__nv_bfloat162*>(&hi[base]) = __nv_bfloat162(h0, h1);
            *reinterpret_cast<__nv_bfloat162*>(&lo[base]) = __nv_bfloat162(l0, l1);
        }
    }
}

// ---------------------------------------------------------------------------
// Kernel 2: scores.  E = exp(Q K^T) split bf16 hi/lo + column partial sums.
// CTA tile 128(i) x 128(j), K=CH=128 in 4 chunks of 32.  8 warps, warp 64x32.
// ---------------------------------------------------------------------------
__global__ void __launch_bounds__(256, 1) scores_kernel()
{
    extern __shared__ char smem[];
    const uint32_t sb = smem_u32(smem);
    const int tid = threadIdx.x, wid = tid >> 5, lane = tid & 31;
    const int g = lane >> 2, t = lane & 3;
    const int wm = wid & 1, wn = wid >> 1;
    const int b = blockIdx.z, i0 = blockIdx.y * 128, j0 = blockIdx.x * 128;

    const bf16* Qh = g_Qhi + ((size_t)b * HW + i0) * CH;
    const bf16* Ql = g_Qlo + ((size_t)b * HW + i0) * CH;
    const bf16* Kh = g_Khi + ((size_t)b * HW + j0) * CH;
    const bf16* Kl = g_Klo + ((size_t)b * HW + j0) * CH;
    const bf16* bases[4] = {Qh, Ql, Kh, Kl};

    float acc[4][4][4];
#pragma unroll
    for (int a = 0; a < 4; a++)
#pragma unroll
        for (int n = 0; n < 4; n++)
#pragma unroll
            for (int r = 0; r < 4; r++) acc[a][n][r] = 0.f;

    // cp.async stage loader: 4 tiles x 128 rows x 4 x 16B
    auto issue = [&](int s, int kc) {
        uint32_t sd = sb + s * STAGE;
#pragma unroll
        for (int w = 0; w < 8; w++) {
            int idx  = tid + w * 256;
            int tile = idx >> 9;
            int row  = (idx >> 2) & 127;
            int seg  = idx & 3;
            cp16(sd + tile * TILE + row * TROW + seg * 16,
                 bases[tile] + (size_t)row * CH + kc * 32 + seg * 8);
        }
    };

    issue(0, 0); cp_commit();
    for (int kc = 0; kc < 4; kc++) {
        int s = kc & 1;
        if (kc < 3) { issue(s ^ 1, kc + 1); cp_commit(); cp_wait<1>(); }
        else        { cp_wait<0>(); }
        __syncthreads();

        const uint32_t SB  = sb + s * STAGE;
        const uint32_t Tah = SB, Tal = SB + TILE, Tbh = SB + 2 * TILE, Tbl = SB + 3 * TILE;
        const uint32_t rowA = (wm * 64 + g) * TROW;
        const uint32_t rowB = (wn * 32 + g) * TROW;
#pragma unroll
        for (int ks = 0; ks < 2; ks++) {
            const uint32_t wo0 = (ks * 8 + t) * 4, wo1 = wo0 + 16;
            uint32_t ah[4][4], al[4][4], bh[4][2], bl[4][2];
#pragma unroll
            for (int mt = 0; mt < 4; mt++) {
                uint32_t o = rowA + mt * (16 * TROW);
                ah[mt][0] = lds32(Tah + o + wo0);
                ah[mt][1] = lds32(Tah + o + 8 * TROW + wo0);
                ah[mt][2] = lds32(Tah + o + wo1);
                ah[mt][3] = lds32(Tah + o + 8 * TROW + wo1);
                al[mt][0] = lds32(Tal + o + wo0);
                al[mt][1] = lds32(Tal + o + 8 * TROW + wo0);
                al[mt][2] = lds32(Tal + o + wo1);
                al[mt][3] = lds32(Tal + o + 8 * TROW + wo1);
            }
#pragma unroll
            for (int nt = 0; nt < 4; nt++) {
                uint32_t o = rowB + nt * (8 * TROW);
                bh[nt][0] = lds32(Tbh + o + wo0);
                bh[nt][1] = lds32(Tbh + o + wo1);
                bl[nt][0] = lds32(Tbl + o + wo0);
                bl[nt][1] = lds32(Tbl + o + wo1);
            }
#pragma unroll
            for (int mt = 0; mt < 4; mt++)
#pragma unroll
                for (int nt = 0; nt < 4; nt++) {
                    mma_bf16(acc[mt][nt], ah[mt], bh[nt]);   // hi*hi
                    mma_bf16(acc[mt][nt], ah[mt], bl[nt]);   // hi*lo
                    mma_bf16(acc[mt][nt], al[mt], bh[nt]);   // lo*hi
                }
        }
        __syncthreads();
    }

    // epilogue: exp, split-store E, column partials
    float csum[4][2] = {};
    const size_t Eb = (size_t)b * HW * HW;
#pragma unroll
    for (int mt = 0; mt < 4; mt++) {
        const int r0 = i0 + wm * 64 + mt * 16 + g;
#pragma unroll
        for (int nt = 0; nt < 4; nt++) {
            const int jj = j0 + wn * 32 + nt * 8 + 2 * t;
            float e0 = __expf(acc[mt][nt][0]);
            float e1 = __expf(acc[mt][nt][1]);
            float e2 = __expf(acc[mt][nt][2]);
            float e3 = __expf(acc[mt][nt][3]);
            csum[nt][0] += e0 + e2;
            csum[nt][1] += e1 + e3;
            bf16 h0, l0, h1, l1, h2, l2, h3, l3;
            split_bf16(e0, h0, l0); split_bf16(e1, h1, l1);
            split_bf16(e2, h2, l2); split_bf16(e3, h3, l3);
            size_t o1 = Eb + (size_t)r0 * HW + jj;
            size_t o2 = o1 + (size_t)8 * HW;
            *reinterpret_cast<__nv_bfloat162*>(&g_Ehi[o1]) = __nv_bfloat162(h0, h1);
            *reinterpret_cast<__nv_bfloat162*>(&g_Elo[o1]) = __nv_bfloat162(l0, l1);
            *reinterpret_cast<__nv_bfloat162*>(&g_Ehi[o2]) = __nv_bfloat162(h2, h3);
            *reinterpret_cast<__nv_bfloat162*>(&g_Elo[o2]) = __nv_bfloat162(l2, l3);
        }
    }
    // reduce csum over the 8 lanes sharing t (xor bits 2,3,4)
#pragma unroll
    for (int nt = 0; nt < 4; nt++)
#pragma unroll
        for (int p = 0; p < 2; p++) {
            float v = csum[nt][p];
            v += __shfl_xor_sync(0xffffffffu, v, 4);
            v += __shfl_xor_sync(0xffffffffu, v, 8);
            v += __shfl_xor_sync(0xffffffffu, v, 16);
            csum[nt][p] = v;
        }
    float* red = reinterpret_cast<float*>(smem);   // reuse stage smem
    if (lane < 4) {
#pragma unroll
        for (int nt = 0; nt < 4; nt++)
#pragma unroll
            for (int p = 0; p < 2; p++)
                red[wm * 128 + wn * 32 + nt * 8 + 2 * lane + p] = csum[nt][p];
    }
    __syncthreads();
    if (tid < 128)
        g_colpart[((b * RB) + blockIdx.y) * HW + j0 + tid] = red[tid] + red[128 + tid];
}

// ---------------------------------------------------------------------------
// Kernel 3: colsum
// ---------------------------------------------------------------------------
__global__ void colsum_kernel()
{
    int tid = blockIdx.x * blockDim.x + threadIdx.x;
    if (tid >= BATCH * HW) return;
    int b = tid / HW, j = tid % HW;
    float s = 0.f;
#pragma unroll 8
    for (int rb = 0; rb < RB; rb++)
        s += g_colpart[((b * RB) + rb) * HW + j];
    g_colsum[tid] = s;
}

// ---------------------------------------------------------------------------
// Kernel 4: V' = V / colsum, bf16 hi/lo split
// ---------------------------------------------------------------------------
__global__ void vnorm_kernel()
{
    int idx = blockIdx.x * blockDim.x + threadIdx.x;
    if (idx >= BATCH * CH * HW) return;
    int j = idx & (HW - 1);
    int b = idx / (CH * HW);
    float v = g_V[idx] / g_colsum[b * HW + j];
    bf16 h, l;
    split_bf16(v, h, l);
    g_Vhi[idx] = h;
    g_Vlo[idx] = l;
}

// ---------------------------------------------------------------------------
// Kernel 5: AV.  out[b][c][i] = X + sum_j E[i][j] V'[c][j]
// m = c (128), n = i (128), k = j (4096 in 128 chunks).  Direct coalesced output.
// ---------------------------------------------------------------------------
__global__ void __launch_bounds__(256, 1) av_kernel(const float* __restrict__ X,
                                                    float* __restrict__ out)
{
    extern __shared__ char smem[];
    const uint32_t sb = smem_u32(smem);
    const int tid = threadIdx.x, wid = tid >> 5, lane = tid & 31;
    const int g = lane >> 2, t = lane & 3;
    const int wm = wid & 1, wn = wid >> 1;
    const int b = blockIdx.y, i0 = blockIdx.x * 128;

    const bf16* Vh = g_Vhi + (size_t)b * CH * HW;
    const bf16* Vl = g_Vlo + (size_t)b * CH * HW;
    const bf16* Eh = g_Ehi + (size_t)b * HW * HW + (size_t)i0 * HW;
    const bf16* El = g_Elo + (size_t)b * HW * HW + (size_t)i0 * HW;
    const bf16* bases[4] = {Vh, Vl, Eh, El};

    float acc[4][4][4];
#pragma unroll
    for (int a = 0; a < 4; a++)
#pragma unroll
        for (int n = 0; n < 4; n++)
#pragma unroll
            for (int r = 0; r < 4; r++) acc[a][n][r] = 0.f;

    auto issue = [&](int s, int kc) {
        uint32_t sd = sb + s * STAGE;
#pragma unroll
        for (int w = 0; w < 8; w++) {
            int idx  = tid + w * 256;
            int tile = idx >> 9;
            int row  = (idx >> 2) & 127;
            int seg  = idx & 3;
            cp16(sd + tile * TILE + row * TROW + seg * 16,
                 bases[tile] + (size_t)row * HW + kc * 32 + seg * 8);
        }
    };

    issue(0, 0); cp_commit();
    for (int kc = 0; kc < 128; kc++) {
        int s = kc & 1;
        if (kc < 127) { issue(s ^ 1, kc + 1); cp_commit(); cp_wait<1>(); }
        else          { cp_wait<0>(); }
        __syncthreads();

        const uint32_t SB  = sb + s * STAGE;
        const uint32_t Tah = SB, Tal = SB + TILE, Tbh = SB + 2 * TILE, Tbl = SB + 3 * TILE;
        const uint32_t rowA = (wm * 64 + g) * TROW;
        const uint32_t rowB = (wn * 32 + g) * TROW;
#pragma unroll
        for (int ks = 0; ks < 2; ks++) {
            const uint32_t wo0 = (ks * 8 + t) * 4, wo1 = wo0 + 16;
            uint32_t ah[4][4], al[4][4], bh[4][2], bl[4][2];
#pragma unroll
            for (int mt = 0; mt < 4; mt++) {
                uint32_t o = rowA + mt * (16 * TROW);
                ah[mt][0] = lds32(Tah + o + wo0);
                ah[mt][1] = lds32(Tah + o + 8 * TROW + wo0);
                ah[mt][2] = lds32(Tah + o + wo1);
                ah[mt][3] = lds32(Tah + o + 8 * TROW + wo1);
                al[mt][0] = lds32(Tal + o + wo0);
                al[mt][1] = lds32(Tal + o + 8 * TROW + wo0);
                al[mt][2] = lds32(Tal + o + wo1);
                al[mt][3] = lds32(Tal + o + 8 * TROW + wo1);
            }
#pragma unroll
            for (int nt = 0; nt < 4; nt++) {
                uint32_t o = rowB + nt * (8 * TROW);
                bh[nt][0] = lds32(Tbh + o + wo0);
                bh[nt][1] = lds32(Tbh + o + wo1);
                bl[nt][0] = lds32(Tbl + o + wo0);
                bl[nt][1] = lds32(Tbl + o + wo1);
            }
#pragma unroll
            for (int mt = 0; mt < 4; mt++)
#pragma unroll
                for (int nt = 0; nt < 4; nt++) {
                    mma_bf16(acc[mt][nt], ah[mt], bh[nt]);   // Vh*Eh
                    mma_bf16(acc[mt][nt], ah[mt], bl[nt]);   // Vh*El
                    mma_bf16(acc[mt][nt], al[mt], bh[nt]);   // Vl*Eh
                }
        }
        __syncthreads();
    }

    // epilogue: residual add + coalesced float2 stores
#pragma unroll
    for (int mt = 0; mt < 4; mt++) {
        const int cr = wm * 64 + mt * 16 + g;
#pragma unroll
        for (int nt = 0; nt < 4; nt++) {
            const int ii = i0 + wn * 32 + nt * 8 + 2 * t;
            size_t o1 = ((size_t)b * CH + cr) * HW + ii;
            size_t o2 = o1 + (size_t)8 * HW;
            float2 x1 = *reinterpret_cast<const float2*>(&X[o1]);
            float2 x2 = *reinterpret_cast<const float2*>(&X[o2]);
            float2 r1 = make_float2(x1.x + acc[mt][nt][0], x1.y + acc[mt][nt][1]);
            float2 r2 = make_float2(x2.x + acc[mt][nt][2], x2.y + acc[mt][nt][3]);
            *reinterpret_cast<float2*>(&out[o1]) = r1;
            *reinterpret_cast<float2*>(&out[o2]) = r2;
        }
    }
}

// ---------------------------------------------------------------------------
extern "C" void kernel_launch(void* const* d_in, const int* in_sizes, int n_in,
                              void* d_out, int out_size)
{
    const float* X  = (const float*)d_in[0];
    const float* Wq = (const float*)d_in[1];
    const float* bq = (const float*)d_in[2];
    const float* Wk = (const float*)d_in[3];
    const float* bk = (const float*)d_in[4];
    const float* Wv = (const float*)d_in[5];
    const float* bv = (const float*)d_in[6];
    float* out = (float*)d_out;

    const int SMEM = 2 * STAGE;   // 81920
    cudaFuncSetAttribute(scores_kernel, cudaFuncAttributeMaxDynamicSharedMemorySize, SMEM);
    cudaFuncSetAttribute(av_kernel,     cudaFuncAttributeMaxDynamicSharedMemorySize, SMEM);

    proj_kernel<<<dim3(HW / 32, 3, BATCH), 128>>>(X, Wq, bq, Wk, bk, Wv, bv);
    scores_kernel<<<dim3(HW / 128, HW / 128, BATCH), 256, SMEM>>>();
    colsum_kernel<<<(BATCH * HW + 255) / 256, 256>>>();
    vnorm_kernel<<<(BATCH * CH * HW + 255) / 256, 256>>>();
    av_kernel<<<dim3(HW / 128, BATCH), 256, SMEM>>>(X, out);
}